// round 8
// baseline (speedup 1.0000x reference)
#include <cuda_runtime.h>
#include <cuda_bf16.h>
#include <cstdint>

#define BB 128
#define LL 256
#define HH 1024
#define TT 9

#define NCH 12
#define CHS 22                    // 12*22 = 264 >= 256

#define EMIS_GRID 296             // 148 SMs x 2 blocks
#define NWARPS_TOT (EMIS_GRID * 8)
#define NSTRIPS (BB * LL / 4)     // 8192 strips of 4 rows

// Scratch (no allocations allowed)
__device__ __align__(16) float g_emis[BB * LL * TT];
__device__ float g_llh[BB];
__device__ int g_ctr;

#define FFMA2(acc, a, b) \
    asm("fma.rn.f32x2 %0, %1, %2, %0;" : "+l"(acc) : "l"(a), "l"(b))

// ---------------------------------------------------------------------------
// Kernel 1: emissions = hidden @ W^T + b.
// 4 rows/warp, packed FFMA2 accumulators (72 regs), W in smem (ratio 2.25),
// streaming __ldcs loads, register-minimal serialized epilogue.
// ---------------------------------------------------------------------------
__global__ __launch_bounds__(256, 2) void emis_kernel(
    const float* __restrict__ hidden,
    const float* __restrict__ W,
    const float* __restrict__ bias)
{
    __shared__ __align__(16) float Ws[TT * HH];
    __shared__ float bs[TT];

    int tid = threadIdx.x;
    {
        const float4* W4 = reinterpret_cast<const float4*>(W);
        float4* Ws4 = reinterpret_cast<float4*>(Ws);
#pragma unroll
        for (int i = 0; i < 9; i++) Ws4[tid + i * 256] = W4[tid + i * 256];
        if (tid < TT) bs[tid] = bias[tid];
    }
    __syncthreads();

    int warp = tid >> 5;
    int lane = tid & 31;
    int gwid = blockIdx.x * 8 + warp;
    const ulonglong2* Ws2 = reinterpret_cast<const ulonglong2*>(Ws);

    for (int strip = gwid; strip < NSTRIPS; strip += NWARPS_TOT) {
        int row0 = strip * 4;
        const ulonglong2* H0 =
            reinterpret_cast<const ulonglong2*>(hidden + (size_t)row0 * HH);

        unsigned long long acc[4][TT];
#pragma unroll
        for (int m = 0; m < 4; m++)
#pragma unroll
            for (int t = 0; t < TT; t++) acc[m][t] = 0ull;

#pragma unroll
        for (int i = 0; i < 8; i++) {
            int kk = lane + 32 * i;
            ulonglong2 h0 = __ldcs(H0 + 0 * 256 + kk);
            ulonglong2 h1 = __ldcs(H0 + 1 * 256 + kk);
            ulonglong2 h2 = __ldcs(H0 + 2 * 256 + kk);
            ulonglong2 h3 = __ldcs(H0 + 3 * 256 + kk);
#pragma unroll
            for (int t = 0; t < TT; t++) {
                ulonglong2 wv = Ws2[t * 256 + kk];
                FFMA2(acc[0][t], h0.x, wv.x);
                FFMA2(acc[0][t], h0.y, wv.y);
                FFMA2(acc[1][t], h1.x, wv.x);
                FFMA2(acc[1][t], h1.y, wv.y);
                FFMA2(acc[2][t], h2.x, wv.x);
                FFMA2(acc[2][t], h2.y, wv.y);
                FFMA2(acc[3][t], h3.x, wv.x);
                FFMA2(acc[3][t], h3.y, wv.y);
            }
        }

        // Serialized epilogue: one (m,t) at a time, minimal live registers.
        // After the xor-butterfly every lane holds the full sum; lane t of
        // the store group picks up row m's value.
#pragma unroll
        for (int m = 0; m < 4; m++) {
            float resm;
#pragma unroll
            for (int t = 0; t < TT; t++) {
                float lo, hi;
                asm("mov.b64 {%0,%1}, %2;" : "=f"(lo), "=f"(hi) : "l"(acc[m][t]));
                float v = lo + hi;
#pragma unroll
                for (int off = 16; off > 0; off >>= 1)
                    v += __shfl_xor_sync(0xffffffffu, v, off);
                if (lane == t) resm = v + bs[t];
            }
            if (lane < TT)
                g_emis[(size_t)(row0 + m) * TT + lane] = resm;  // 36B run
        }
    }
}

// ---------------------------------------------------------------------------
// Kernel 2: chunk-parallel CRF forward. One block (256 thr) per batch.
// 12 chunks x 9 columns = 108 tasks on 4 warps. NO launch_bounds: E[81]
// must stay register-resident (255-reg budget). Fused final reduce.
// ---------------------------------------------------------------------------
__global__ void crf_kernel(
    const float* __restrict__ start_t,
    const float* __restrict__ end_t,
    const float* __restrict__ trans,
    const int*   __restrict__ labels,
    const int*   __restrict__ lengths,
    float* __restrict__ out)
{
    __shared__ __align__(16) float em_s[LL * TT];
    __shared__ __align__(16) float u_s[LL * 12];   // stride 12 for float4 LDS
    __shared__ float tr_s[TT * TT];
    __shared__ float Etr_s[TT * TT];
    __shared__ float st_s[TT];
    __shared__ float en_s[TT];
    __shared__ __align__(16) int lab_s[LL];
    __shared__ float P_s[NCH][TT][TT];
    __shared__ int   e_s[NCH][TT];
    __shared__ float num_red[8];

    int b = blockIdx.x;
    int tid = threadIdx.x;
    int lane = tid & 31;
    int w = tid >> 5;

    // ---- loads ----
    {
        const float4* src = reinterpret_cast<const float4*>(g_emis + (size_t)b * LL * TT);
        float4* dst = reinterpret_cast<float4*>(em_s);
        for (int i = tid; i < LL * TT / 4; i += 256) dst[i] = src[i];
    }
    if (tid < LL / 4) {
        reinterpret_cast<int4*>(lab_s)[tid] =
            reinterpret_cast<const int4*>(labels + (size_t)b * LL)[tid];
    }
    if (tid < TT * TT) {
        float tv = trans[tid];
        tr_s[tid] = tv;
        Etr_s[tid] = __expf(tv);
    }
    if (tid < TT) { st_s[tid] = start_t[tid]; en_s[tid] = end_t[tid]; }
    int len = lengths[b];
    __syncthreads();

    // ---- u = exp(em) into padded layout; numerator partials ----
    for (int i = tid; i < LL * TT; i += 256) {
        int t = i / TT, k = i - t * TT;
        u_s[t * 12 + k] = __expf(em_s[i]);
    }
    float num_p = 0.0f;
    for (int t = 1 + tid; t < len; t += 256) {
        int pv = lab_s[t - 1], cu = lab_s[t];
        num_p += tr_s[pv * TT + cu] + em_s[t * TT + cu];
    }
#pragma unroll
    for (int off = 16; off > 0; off >>= 1)
        num_p += __shfl_xor_sync(0xffffffffu, num_p, off);
    if (lane == 0) num_red[w] = num_p;
    __syncthreads();

    // ---- chunked column scan: task = (chunk c, column j) ----
    int task = w * 32 + lane;
    if (task < NCH * TT) {
        int c = task / TT;
        int j = task - c * TT;
        int lo = (c == 0) ? 1 : CHS * c;
        int hi = min(CHS * (c + 1), len);

        float E[TT * TT];
#pragma unroll
        for (int i = 0; i < TT * TT; i++) E[i] = Etr_s[i];

        float P[TT];
#pragma unroll
        for (int k = 0; k < TT; k++) P[k] = (k == j) ? 1.0f : 0.0f;
        int esum = 0;

        for (int t = hi - 1; t >= lo; t--) {
            float4 ua = *reinterpret_cast<const float4*>(&u_s[t * 12]);
            float4 ub = *reinterpret_cast<const float4*>(&u_s[t * 12 + 4]);
            float u8 = u_s[t * 12 + 8];
            float wv[TT];
            wv[0] = ua.x * P[0]; wv[1] = ua.y * P[1]; wv[2] = ua.z * P[2];
            wv[3] = ua.w * P[3]; wv[4] = ub.x * P[4]; wv[5] = ub.y * P[5];
            wv[6] = ub.z * P[6]; wv[7] = ub.w * P[7]; wv[8] = u8   * P[8];
            float np[TT];
#pragma unroll
            for (int i = 0; i < TT; i++) {
                float s = E[i * TT] * wv[0];
#pragma unroll
                for (int k = 1; k < TT; k++) s += E[i * TT + k] * wv[k];
                np[i] = s;
            }
#pragma unroll
            for (int i = 0; i < TT; i++) P[i] = np[i];

            if (((hi - t) & 3) == 0) {
                int e = (__float_as_int(P[0]) >> 23) & 255;
                float rr = __int_as_float((254 - e) << 23);  // exact 2^(127-e)
                esum += e - 127;
#pragma unroll
                for (int i = 0; i < TT; i++) P[i] *= rr;
            }
        }
#pragma unroll
        for (int k = 0; k < TT; k++) P_s[c][k][j] = P[k];
        e_s[c][j] = esum;
    }
    __syncthreads();

    // ---- combine (warp 0, lane-parallel over columns) ----
    if (w == 0) {
        float v[TT];
        int G = 0;
#pragma unroll
        for (int k = 0; k < TT; k++) v[k] = __expf(st_s[k] + em_s[k]);

        int jj = (lane < TT) ? lane : 0;

#pragma unroll
        for (int c = 0; c < NCH; c++) {
            float s = v[0] * P_s[c][0][jj];
#pragma unroll
            for (int k = 1; k < TT; k++) s += v[k] * P_s[c][k][jj];

            float nv[TT];
#pragma unroll
            for (int k = 0; k < TT; k++) nv[k] = __shfl_sync(0xffffffffu, s, k);

            int ec[TT];
#pragma unroll
            for (int k = 0; k < TT; k++) ec[k] = e_s[c][k];

            int Tk[TT], Tmax;
#pragma unroll
            for (int k = 0; k < TT; k++)
                Tk[k] = G + ec[k] + ((__float_as_int(nv[k]) >> 23) & 255);
            Tmax = Tk[0];
#pragma unroll
            for (int k = 1; k < TT; k++) Tmax = max(Tmax, Tk[k]);
            int Gnew = Tmax - 127;
#pragma unroll
            for (int k = 0; k < TT; k++) {
                int d = G + ec[k] - Gnew;
                v[k] = (d < -126) ? 0.0f : nv[k] * __int_as_float((127 + d) << 23);
            }
            G = Gnew;
        }

        float tot = 0.0f;
#pragma unroll
        for (int k = 0; k < TT; k++) tot += v[k] * __expf(en_s[k]);
        float denom = __logf(tot) + (float)G * 0.6931471805599453f;

        float ns = (lane < 8) ? num_red[lane] : 0.0f;
#pragma unroll
        for (int off = 4; off > 0; off >>= 1)
            ns += __shfl_xor_sync(0xffffffffu, ns, off);
        ns = __shfl_sync(0xffffffffu, ns, 0);
        int tag0 = lab_s[0];
        float num = ns + st_s[tag0] + em_s[tag0] + en_s[lab_s[len - 1]];

        if (lane == 0) g_llh[b] = num - denom;

        // ---- fused finalization ----
        __threadfence();
        __syncwarp();
        int last = 0;
        if (lane == 0) {
            int old = atomicAdd(&g_ctr, 1);
            last = (old == BB - 1);
        }
        last = __shfl_sync(0xffffffffu, last, 0);
        if (last) {
            __threadfence();
            float vv = 0.0f;
#pragma unroll
            for (int i = 0; i < BB / 32; i++) vv += g_llh[lane + 32 * i];
#pragma unroll
            for (int off = 16; off > 0; off >>= 1)
                vv += __shfl_xor_sync(0xffffffffu, vv, off);
            if (lane == 0) {
                out[0] = -vv * (1.0f / (float)BB);
                g_ctr = 0;  // self-reset for graph replay
            }
        }
    }
}

extern "C" void kernel_launch(void* const* d_in, const int* in_sizes, int n_in,
                              void* d_out, int out_size)
{
    const float* hidden  = (const float*)d_in[0];
    const float* W       = (const float*)d_in[1];
    const float* bias    = (const float*)d_in[2];
    const float* start_t = (const float*)d_in[3];
    const float* end_t   = (const float*)d_in[4];
    const float* trans   = (const float*)d_in[5];
    const int*   labels  = (const int*)d_in[6];
    const int*   lengths = (const int*)d_in[7];
    float* out = (float*)d_out;

    emis_kernel<<<EMIS_GRID, 256>>>(hidden, W, bias);
    crf_kernel<<<BB, 256>>>(start_t, end_t, trans, labels, lengths, out);
}

// round 9
// speedup vs baseline: 1.0069x; 1.0069x over previous
#include <cuda_runtime.h>
#include <cuda_bf16.h>
#include <cstdint>

#define BB 128
#define LL 256
#define HH 1024
#define TT 9

#define NCH 12
#define CHS 22                    // 12*22 = 264 >= 256

#define EMIS_GRID 296             // 148 SMs x 2 blocks
#define NWARPS_TOT (EMIS_GRID * 8)
#define NSTRIPS (BB * LL / 4)     // 8192 strips of 4 rows

// Scratch (no allocations allowed)
__device__ __align__(16) float g_emis[BB * LL * TT];
__device__ float g_llh[BB];
__device__ int g_ctr;

#define FFMA2(acc, a, b) \
    asm("fma.rn.f32x2 %0, %1, %2, %0;" : "+l"(acc) : "l"(a), "l"(b))

// ---------------------------------------------------------------------------
// Kernel 1: emissions = hidden @ W^T + b.
// 4 rows/warp, packed FFMA2 accumulators (72 regs), W in smem (ratio 2.25),
// streaming __ldcs loads, register-minimal serialized epilogue.
// ---------------------------------------------------------------------------
__global__ __launch_bounds__(256, 2) void emis_kernel(
    const float* __restrict__ hidden,
    const float* __restrict__ W,
    const float* __restrict__ bias)
{
    __shared__ __align__(16) float Ws[TT * HH];
    __shared__ float bs[TT];

    int tid = threadIdx.x;
    {
        const float4* W4 = reinterpret_cast<const float4*>(W);
        float4* Ws4 = reinterpret_cast<float4*>(Ws);
#pragma unroll
        for (int i = 0; i < 9; i++) Ws4[tid + i * 256] = W4[tid + i * 256];
        if (tid < TT) bs[tid] = bias[tid];
    }
    __syncthreads();

    int warp = tid >> 5;
    int lane = tid & 31;
    int gwid = blockIdx.x * 8 + warp;
    const ulonglong2* Ws2 = reinterpret_cast<const ulonglong2*>(Ws);

    for (int strip = gwid; strip < NSTRIPS; strip += NWARPS_TOT) {
        int row0 = strip * 4;
        const ulonglong2* H0 =
            reinterpret_cast<const ulonglong2*>(hidden + (size_t)row0 * HH);

        unsigned long long acc[4][TT];
#pragma unroll
        for (int m = 0; m < 4; m++)
#pragma unroll
            for (int t = 0; t < TT; t++) acc[m][t] = 0ull;

#pragma unroll
        for (int i = 0; i < 8; i++) {
            int kk = lane + 32 * i;
            ulonglong2 h0 = __ldcs(H0 + 0 * 256 + kk);
            ulonglong2 h1 = __ldcs(H0 + 1 * 256 + kk);
            ulonglong2 h2 = __ldcs(H0 + 2 * 256 + kk);
            ulonglong2 h3 = __ldcs(H0 + 3 * 256 + kk);
#pragma unroll
            for (int t = 0; t < TT; t++) {
                ulonglong2 wv = Ws2[t * 256 + kk];
                FFMA2(acc[0][t], h0.x, wv.x);
                FFMA2(acc[0][t], h0.y, wv.y);
                FFMA2(acc[1][t], h1.x, wv.x);
                FFMA2(acc[1][t], h1.y, wv.y);
                FFMA2(acc[2][t], h2.x, wv.x);
                FFMA2(acc[2][t], h2.y, wv.y);
                FFMA2(acc[3][t], h3.x, wv.x);
                FFMA2(acc[3][t], h3.y, wv.y);
            }
        }

        // Serialized epilogue: one (m,t) at a time, minimal live registers.
        // After the xor-butterfly every lane holds the full sum; lane t of
        // the store group picks up row m's value.
#pragma unroll
        for (int m = 0; m < 4; m++) {
            float resm;
#pragma unroll
            for (int t = 0; t < TT; t++) {
                float lo, hi;
                asm("mov.b64 {%0,%1}, %2;" : "=f"(lo), "=f"(hi) : "l"(acc[m][t]));
                float v = lo + hi;
#pragma unroll
                for (int off = 16; off > 0; off >>= 1)
                    v += __shfl_xor_sync(0xffffffffu, v, off);
                if (lane == t) resm = v + bs[t];
            }
            if (lane < TT)
                g_emis[(size_t)(row0 + m) * TT + lane] = resm;  // 36B run
        }
    }
}

// ---------------------------------------------------------------------------
// Kernel 2: chunk-parallel CRF forward. One block (256 thr) per batch.
// 12 chunks x 9 columns = 108 tasks on 4 warps. NO launch_bounds: E[81]
// must stay register-resident (255-reg budget). Fused final reduce.
// ---------------------------------------------------------------------------
__global__ void crf_kernel(
    const float* __restrict__ start_t,
    const float* __restrict__ end_t,
    const float* __restrict__ trans,
    const int*   __restrict__ labels,
    const int*   __restrict__ lengths,
    float* __restrict__ out)
{
    __shared__ __align__(16) float em_s[LL * TT];
    __shared__ __align__(16) float u_s[LL * 12];   // stride 12 for float4 LDS
    __shared__ float tr_s[TT * TT];
    __shared__ float Etr_s[TT * TT];
    __shared__ float st_s[TT];
    __shared__ float en_s[TT];
    __shared__ __align__(16) int lab_s[LL];
    __shared__ float P_s[NCH][TT][TT];
    __shared__ int   e_s[NCH][TT];
    __shared__ float num_red[8];

    int b = blockIdx.x;
    int tid = threadIdx.x;
    int lane = tid & 31;
    int w = tid >> 5;

    // ---- loads ----
    {
        const float4* src = reinterpret_cast<const float4*>(g_emis + (size_t)b * LL * TT);
        float4* dst = reinterpret_cast<float4*>(em_s);
        for (int i = tid; i < LL * TT / 4; i += 256) dst[i] = src[i];
    }
    if (tid < LL / 4) {
        reinterpret_cast<int4*>(lab_s)[tid] =
            reinterpret_cast<const int4*>(labels + (size_t)b * LL)[tid];
    }
    if (tid < TT * TT) {
        float tv = trans[tid];
        tr_s[tid] = tv;
        Etr_s[tid] = __expf(tv);
    }
    if (tid < TT) { st_s[tid] = start_t[tid]; en_s[tid] = end_t[tid]; }
    int len = lengths[b];
    __syncthreads();

    // ---- u = exp(em) into padded layout; numerator partials ----
    for (int i = tid; i < LL * TT; i += 256) {
        int t = i / TT, k = i - t * TT;
        u_s[t * 12 + k] = __expf(em_s[i]);
    }
    float num_p = 0.0f;
    for (int t = 1 + tid; t < len; t += 256) {
        int pv = lab_s[t - 1], cu = lab_s[t];
        num_p += tr_s[pv * TT + cu] + em_s[t * TT + cu];
    }
#pragma unroll
    for (int off = 16; off > 0; off >>= 1)
        num_p += __shfl_xor_sync(0xffffffffu, num_p, off);
    if (lane == 0) num_red[w] = num_p;
    __syncthreads();

    // ---- chunked column scan: task = (chunk c, column j) ----
    int task = w * 32 + lane;
    if (task < NCH * TT) {
        int c = task / TT;
        int j = task - c * TT;
        int lo = (c == 0) ? 1 : CHS * c;
        int hi = min(CHS * (c + 1), len);

        float E[TT * TT];
#pragma unroll
        for (int i = 0; i < TT * TT; i++) E[i] = Etr_s[i];

        float P[TT];
#pragma unroll
        for (int k = 0; k < TT; k++) P[k] = (k == j) ? 1.0f : 0.0f;
        int esum = 0;

        for (int t = hi - 1; t >= lo; t--) {
            float4 ua = *reinterpret_cast<const float4*>(&u_s[t * 12]);
            float4 ub = *reinterpret_cast<const float4*>(&u_s[t * 12 + 4]);
            float u8 = u_s[t * 12 + 8];
            float wv[TT];
            wv[0] = ua.x * P[0]; wv[1] = ua.y * P[1]; wv[2] = ua.z * P[2];
            wv[3] = ua.w * P[3]; wv[4] = ub.x * P[4]; wv[5] = ub.y * P[5];
            wv[6] = ub.z * P[6]; wv[7] = ub.w * P[7]; wv[8] = u8   * P[8];
            float np[TT];
#pragma unroll
            for (int i = 0; i < TT; i++) {
                float s = E[i * TT] * wv[0];
#pragma unroll
                for (int k = 1; k < TT; k++) s += E[i * TT + k] * wv[k];
                np[i] = s;
            }
#pragma unroll
            for (int i = 0; i < TT; i++) P[i] = np[i];

            if (((hi - t) & 3) == 0) {
                int e = (__float_as_int(P[0]) >> 23) & 255;
                float rr = __int_as_float((254 - e) << 23);  // exact 2^(127-e)
                esum += e - 127;
#pragma unroll
                for (int i = 0; i < TT; i++) P[i] *= rr;
            }
        }
#pragma unroll
        for (int k = 0; k < TT; k++) P_s[c][k][j] = P[k];
        e_s[c][j] = esum;
    }
    __syncthreads();

    // ---- combine (warp 0, lane-parallel over columns) ----
    if (w == 0) {
        float v[TT];
        int G = 0;
#pragma unroll
        for (int k = 0; k < TT; k++) v[k] = __expf(st_s[k] + em_s[k]);

        int jj = (lane < TT) ? lane : 0;

#pragma unroll
        for (int c = 0; c < NCH; c++) {
            float s = v[0] * P_s[c][0][jj];
#pragma unroll
            for (int k = 1; k < TT; k++) s += v[k] * P_s[c][k][jj];

            float nv[TT];
#pragma unroll
            for (int k = 0; k < TT; k++) nv[k] = __shfl_sync(0xffffffffu, s, k);

            int ec[TT];
#pragma unroll
            for (int k = 0; k < TT; k++) ec[k] = e_s[c][k];

            int Tk[TT], Tmax;
#pragma unroll
            for (int k = 0; k < TT; k++)
                Tk[k] = G + ec[k] + ((__float_as_int(nv[k]) >> 23) & 255);
            Tmax = Tk[0];
#pragma unroll
            for (int k = 1; k < TT; k++) Tmax = max(Tmax, Tk[k]);
            int Gnew = Tmax - 127;
#pragma unroll
            for (int k = 0; k < TT; k++) {
                int d = G + ec[k] - Gnew;
                v[k] = (d < -126) ? 0.0f : nv[k] * __int_as_float((127 + d) << 23);
            }
            G = Gnew;
        }

        float tot = 0.0f;
#pragma unroll
        for (int k = 0; k < TT; k++) tot += v[k] * __expf(en_s[k]);
        float denom = __logf(tot) + (float)G * 0.6931471805599453f;

        float ns = (lane < 8) ? num_red[lane] : 0.0f;
#pragma unroll
        for (int off = 4; off > 0; off >>= 1)
            ns += __shfl_xor_sync(0xffffffffu, ns, off);
        ns = __shfl_sync(0xffffffffu, ns, 0);
        int tag0 = lab_s[0];
        float num = ns + st_s[tag0] + em_s[tag0] + en_s[lab_s[len - 1]];

        if (lane == 0) g_llh[b] = num - denom;

        // ---- fused finalization ----
        __threadfence();
        __syncwarp();
        int last = 0;
        if (lane == 0) {
            int old = atomicAdd(&g_ctr, 1);
            last = (old == BB - 1);
        }
        last = __shfl_sync(0xffffffffu, last, 0);
        if (last) {
            __threadfence();
            float vv = 0.0f;
#pragma unroll
            for (int i = 0; i < BB / 32; i++) vv += g_llh[lane + 32 * i];
#pragma unroll
            for (int off = 16; off > 0; off >>= 1)
                vv += __shfl_xor_sync(0xffffffffu, vv, off);
            if (lane == 0) {
                out[0] = -vv * (1.0f / (float)BB);
                g_ctr = 0;  // self-reset for graph replay
            }
        }
    }
}

extern "C" void kernel_launch(void* const* d_in, const int* in_sizes, int n_in,
                              void* d_out, int out_size)
{
    const float* hidden  = (const float*)d_in[0];
    const float* W       = (const float*)d_in[1];
    const float* bias    = (const float*)d_in[2];
    const float* start_t = (const float*)d_in[3];
    const float* end_t   = (const float*)d_in[4];
    const float* trans   = (const float*)d_in[5];
    const int*   labels  = (const int*)d_in[6];
    const int*   lengths = (const int*)d_in[7];
    float* out = (float*)d_out;

    emis_kernel<<<EMIS_GRID, 256>>>(hidden, W, bias);
    crf_kernel<<<BB, 256>>>(start_t, end_t, trans, labels, lengths, out);
}

// round 10
// speedup vs baseline: 1.0131x; 1.0062x over previous
#include <cuda_runtime.h>
#include <cuda_bf16.h>
#include <cstdint>

#define BB 128
#define LL 256
#define HH 1024
#define TT 9

#define NCH 12
#define CHS 22                    // 12*22 = 264 >= 256

#define EMIS_GRID 296             // 148 SMs x 2 blocks
#define NWARPS_TOT (EMIS_GRID * 8)
#define NSTRIPS (BB * LL / 4)     // 8192 strips of 4 rows

// Scratch (no allocations allowed)
__device__ __align__(16) float g_emis[BB * LL * TT];
__device__ float g_llh[BB];
__device__ int g_ctr;

#define FFMA2(acc, a, b) \
    asm("fma.rn.f32x2 %0, %1, %2, %0;" : "+l"(acc) : "l"(a), "l"(b))

// ---------------------------------------------------------------------------
// Kernel 1: emissions = hidden @ W^T + b.
// 4 rows/warp, packed FFMA2 accumulators (72 regs), W in smem (ratio 2.25),
// streaming __ldcs loads, register-minimal serialized epilogue.
// ---------------------------------------------------------------------------
__global__ __launch_bounds__(256, 2) void emis_kernel(
    const float* __restrict__ hidden,
    const float* __restrict__ W,
    const float* __restrict__ bias)
{
    __shared__ __align__(16) float Ws[TT * HH];
    __shared__ float bs[TT];

    int tid = threadIdx.x;
    {
        const float4* W4 = reinterpret_cast<const float4*>(W);
        float4* Ws4 = reinterpret_cast<float4*>(Ws);
#pragma unroll
        for (int i = 0; i < 9; i++) Ws4[tid + i * 256] = W4[tid + i * 256];
        if (tid < TT) bs[tid] = bias[tid];
    }
    __syncthreads();

    int warp = tid >> 5;
    int lane = tid & 31;
    int gwid = blockIdx.x * 8 + warp;
    const ulonglong2* Ws2 = reinterpret_cast<const ulonglong2*>(Ws);

    for (int strip = gwid; strip < NSTRIPS; strip += NWARPS_TOT) {
        int row0 = strip * 4;
        const ulonglong2* H0 =
            reinterpret_cast<const ulonglong2*>(hidden + (size_t)row0 * HH);

        unsigned long long acc[4][TT];
#pragma unroll
        for (int m = 0; m < 4; m++)
#pragma unroll
            for (int t = 0; t < TT; t++) acc[m][t] = 0ull;

#pragma unroll
        for (int i = 0; i < 8; i++) {
            int kk = lane + 32 * i;
            ulonglong2 h0 = __ldcs(H0 + 0 * 256 + kk);
            ulonglong2 h1 = __ldcs(H0 + 1 * 256 + kk);
            ulonglong2 h2 = __ldcs(H0 + 2 * 256 + kk);
            ulonglong2 h3 = __ldcs(H0 + 3 * 256 + kk);
#pragma unroll
            for (int t = 0; t < TT; t++) {
                ulonglong2 wv = Ws2[t * 256 + kk];
                FFMA2(acc[0][t], h0.x, wv.x);
                FFMA2(acc[0][t], h0.y, wv.y);
                FFMA2(acc[1][t], h1.x, wv.x);
                FFMA2(acc[1][t], h1.y, wv.y);
                FFMA2(acc[2][t], h2.x, wv.x);
                FFMA2(acc[2][t], h2.y, wv.y);
                FFMA2(acc[3][t], h3.x, wv.x);
                FFMA2(acc[3][t], h3.y, wv.y);
            }
        }

        // Serialized epilogue: one (m,t) at a time, minimal live registers.
        // After the xor-butterfly every lane holds the full sum; lane t of
        // the store group picks up row m's value.
#pragma unroll
        for (int m = 0; m < 4; m++) {
            float resm;
#pragma unroll
            for (int t = 0; t < TT; t++) {
                float lo, hi;
                asm("mov.b64 {%0,%1}, %2;" : "=f"(lo), "=f"(hi) : "l"(acc[m][t]));
                float v = lo + hi;
#pragma unroll
                for (int off = 16; off > 0; off >>= 1)
                    v += __shfl_xor_sync(0xffffffffu, v, off);
                if (lane == t) resm = v + bs[t];
            }
            if (lane < TT)
                g_emis[(size_t)(row0 + m) * TT + lane] = resm;  // 36B run
        }
    }
}

// ---------------------------------------------------------------------------
// Kernel 2: chunk-parallel CRF forward. One block (256 thr) per batch.
// 12 chunks x 9 columns = 108 tasks on 4 warps. NO launch_bounds: E[81]
// must stay register-resident (255-reg budget). Fused final reduce.
// ---------------------------------------------------------------------------
__global__ void crf_kernel(
    const float* __restrict__ start_t,
    const float* __restrict__ end_t,
    const float* __restrict__ trans,
    const int*   __restrict__ labels,
    const int*   __restrict__ lengths,
    float* __restrict__ out)
{
    __shared__ __align__(16) float em_s[LL * TT];
    __shared__ __align__(16) float u_s[LL * 12];   // stride 12 for float4 LDS
    __shared__ float tr_s[TT * TT];
    __shared__ float Etr_s[TT * TT];
    __shared__ float st_s[TT];
    __shared__ float en_s[TT];
    __shared__ __align__(16) int lab_s[LL];
    __shared__ float P_s[NCH][TT][TT];
    __shared__ int   e_s[NCH][TT];
    __shared__ float num_red[8];

    int b = blockIdx.x;
    int tid = threadIdx.x;
    int lane = tid & 31;
    int w = tid >> 5;

    // ---- loads ----
    {
        const float4* src = reinterpret_cast<const float4*>(g_emis + (size_t)b * LL * TT);
        float4* dst = reinterpret_cast<float4*>(em_s);
        for (int i = tid; i < LL * TT / 4; i += 256) dst[i] = src[i];
    }
    if (tid < LL / 4) {
        reinterpret_cast<int4*>(lab_s)[tid] =
            reinterpret_cast<const int4*>(labels + (size_t)b * LL)[tid];
    }
    if (tid < TT * TT) {
        float tv = trans[tid];
        tr_s[tid] = tv;
        Etr_s[tid] = __expf(tv);
    }
    if (tid < TT) { st_s[tid] = start_t[tid]; en_s[tid] = end_t[tid]; }
    int len = lengths[b];
    __syncthreads();

    // ---- u = exp(em) into padded layout; numerator partials ----
    for (int i = tid; i < LL * TT; i += 256) {
        int t = i / TT, k = i - t * TT;
        u_s[t * 12 + k] = __expf(em_s[i]);
    }
    float num_p = 0.0f;
    for (int t = 1 + tid; t < len; t += 256) {
        int pv = lab_s[t - 1], cu = lab_s[t];
        num_p += tr_s[pv * TT + cu] + em_s[t * TT + cu];
    }
#pragma unroll
    for (int off = 16; off > 0; off >>= 1)
        num_p += __shfl_xor_sync(0xffffffffu, num_p, off);
    if (lane == 0) num_red[w] = num_p;
    __syncthreads();

    // ---- chunked column scan: task = (chunk c, column j) ----
    int task = w * 32 + lane;
    if (task < NCH * TT) {
        int c = task / TT;
        int j = task - c * TT;
        int lo = (c == 0) ? 1 : CHS * c;
        int hi = min(CHS * (c + 1), len);

        float E[TT * TT];
#pragma unroll
        for (int i = 0; i < TT * TT; i++) E[i] = Etr_s[i];

        float P[TT];
#pragma unroll
        for (int k = 0; k < TT; k++) P[k] = (k == j) ? 1.0f : 0.0f;
        int esum = 0;

        for (int t = hi - 1; t >= lo; t--) {
            float4 ua = *reinterpret_cast<const float4*>(&u_s[t * 12]);
            float4 ub = *reinterpret_cast<const float4*>(&u_s[t * 12 + 4]);
            float u8 = u_s[t * 12 + 8];
            float wv[TT];
            wv[0] = ua.x * P[0]; wv[1] = ua.y * P[1]; wv[2] = ua.z * P[2];
            wv[3] = ua.w * P[3]; wv[4] = ub.x * P[4]; wv[5] = ub.y * P[5];
            wv[6] = ub.z * P[6]; wv[7] = ub.w * P[7]; wv[8] = u8   * P[8];
            float np[TT];
#pragma unroll
            for (int i = 0; i < TT; i++) {
                float s = E[i * TT] * wv[0];
#pragma unroll
                for (int k = 1; k < TT; k++) s += E[i * TT + k] * wv[k];
                np[i] = s;
            }
#pragma unroll
            for (int i = 0; i < TT; i++) P[i] = np[i];

            if (((hi - t) & 3) == 0) {
                int e = (__float_as_int(P[0]) >> 23) & 255;
                float rr = __int_as_float((254 - e) << 23);  // exact 2^(127-e)
                esum += e - 127;
#pragma unroll
                for (int i = 0; i < TT; i++) P[i] *= rr;
            }
        }
#pragma unroll
        for (int k = 0; k < TT; k++) P_s[c][k][j] = P[k];
        e_s[c][j] = esum;
    }
    __syncthreads();

    // ---- combine (warp 0, lane-parallel over columns) ----
    if (w == 0) {
        float v[TT];
        int G = 0;
#pragma unroll
        for (int k = 0; k < TT; k++) v[k] = __expf(st_s[k] + em_s[k]);

        int jj = (lane < TT) ? lane : 0;

#pragma unroll
        for (int c = 0; c < NCH; c++) {
            float s = v[0] * P_s[c][0][jj];
#pragma unroll
            for (int k = 1; k < TT; k++) s += v[k] * P_s[c][k][jj];

            float nv[TT];
#pragma unroll
            for (int k = 0; k < TT; k++) nv[k] = __shfl_sync(0xffffffffu, s, k);

            int ec[TT];
#pragma unroll
            for (int k = 0; k < TT; k++) ec[k] = e_s[c][k];

            int Tk[TT], Tmax;
#pragma unroll
            for (int k = 0; k < TT; k++)
                Tk[k] = G + ec[k] + ((__float_as_int(nv[k]) >> 23) & 255);
            Tmax = Tk[0];
#pragma unroll
            for (int k = 1; k < TT; k++) Tmax = max(Tmax, Tk[k]);
            int Gnew = Tmax - 127;
#pragma unroll
            for (int k = 0; k < TT; k++) {
                int d = G + ec[k] - Gnew;
                v[k] = (d < -126) ? 0.0f : nv[k] * __int_as_float((127 + d) << 23);
            }
            G = Gnew;
        }

        float tot = 0.0f;
#pragma unroll
        for (int k = 0; k < TT; k++) tot += v[k] * __expf(en_s[k]);
        float denom = __logf(tot) + (float)G * 0.6931471805599453f;

        float ns = (lane < 8) ? num_red[lane] : 0.0f;
#pragma unroll
        for (int off = 4; off > 0; off >>= 1)
            ns += __shfl_xor_sync(0xffffffffu, ns, off);
        ns = __shfl_sync(0xffffffffu, ns, 0);
        int tag0 = lab_s[0];
        float num = ns + st_s[tag0] + em_s[tag0] + en_s[lab_s[len - 1]];

        if (lane == 0) g_llh[b] = num - denom;

        // ---- fused finalization ----
        __threadfence();
        __syncwarp();
        int last = 0;
        if (lane == 0) {
            int old = atomicAdd(&g_ctr, 1);
            last = (old == BB - 1);
        }
        last = __shfl_sync(0xffffffffu, last, 0);
        if (last) {
            __threadfence();
            float vv = 0.0f;
#pragma unroll
            for (int i = 0; i < BB / 32; i++) vv += g_llh[lane + 32 * i];
#pragma unroll
            for (int off = 16; off > 0; off >>= 1)
                vv += __shfl_xor_sync(0xffffffffu, vv, off);
            if (lane == 0) {
                out[0] = -vv * (1.0f / (float)BB);
                g_ctr = 0;  // self-reset for graph replay
            }
        }
    }
}

extern "C" void kernel_launch(void* const* d_in, const int* in_sizes, int n_in,
                              void* d_out, int out_size)
{
    const float* hidden  = (const float*)d_in[0];
    const float* W       = (const float*)d_in[1];
    const float* bias    = (const float*)d_in[2];
    const float* start_t = (const float*)d_in[3];
    const float* end_t   = (const float*)d_in[4];
    const float* trans   = (const float*)d_in[5];
    const int*   labels  = (const int*)d_in[6];
    const int*   lengths = (const int*)d_in[7];
    float* out = (float*)d_out;

    emis_kernel<<<EMIS_GRID, 256>>>(hidden, W, bias);
    crf_kernel<<<BB, 256>>>(start_t, end_t, trans, labels, lengths, out);
}